// round 2
// baseline (speedup 1.0000x reference)
#include <cuda_runtime.h>
#include <cstdint>

#define BB 4
#define NN 1024
#define DD 768
#define HH 12
#define HD 64
#define BH 48
#define KTH 104857

// ---------------- scratch ----------------
__device__ float g_qkv[4096 * 2304];
__device__ float g_attn[(size_t)48 * 1024 * 1024];
__device__ float g_ao[4096 * 768];
__device__ unsigned g_hist[48 * 2048];
__device__ unsigned g_sel[48];
__device__ int g_krem[48];
__device__ float g_thr[48];
__device__ unsigned g_cand[(size_t)48 * 1048576];
__device__ int g_ccnt[48];

__device__ __forceinline__ unsigned fkey(float f) {
    unsigned u = __float_as_uint(f);
    return (u & 0x80000000u) ? ~u : (u ^ 0x80000000u);
}

// ---------------- mma helpers ----------------
__device__ __forceinline__ unsigned cvt_tf32(float f) {
    unsigned r;
    asm("cvt.rna.tf32.f32 %0, %1;" : "=r"(r) : "f"(f));
    return r;
}
__device__ __forceinline__ void mma_tf32(float c[4], unsigned a0, unsigned a1,
                                         unsigned a2, unsigned a3,
                                         unsigned b0, unsigned b1) {
    asm volatile(
        "mma.sync.aligned.m16n8k8.row.col.f32.tf32.tf32.f32 "
        "{%0,%1,%2,%3}, {%4,%5,%6,%7}, {%8,%9}, {%0,%1,%2,%3};"
        : "+f"(c[0]), "+f"(c[1]), "+f"(c[2]), "+f"(c[3])
        : "r"(a0), "r"(a1), "r"(a2), "r"(a3), "r"(b0), "r"(b1));
}
__device__ __forceinline__ void cp16(void* dst, const void* src) {
    unsigned d = (unsigned)__cvta_generic_to_shared(dst);
    asm volatile("cp.async.cg.shared.global [%0], [%1], 16;" :: "r"(d), "l"(src));
}
#define CPCOMMIT asm volatile("cp.async.commit_group;")
#define CPWAIT(N) asm volatile("cp.async.wait_group %0;" :: "n"(N))

// ---------------------------------------------------------------------------
// Projection GEMM: C[M,N] = A[M,K] @ B[K,N] + bias.  128x128x16 tf32 mma.
// ---------------------------------------------------------------------------
__global__ void __launch_bounds__(256) mm_proj(
    const float* __restrict__ A, const float* __restrict__ B,
    const float* __restrict__ bias, float* __restrict__ C,
    int N, int K) {
    __shared__ __align__(16) float As[2][128][20];
    __shared__ __align__(16) float Bs[2][16][136];
    int t = threadIdx.x, lane = t & 31, warp = t >> 5;
    int wm = (warp >> 2) * 64, wn = (warp & 3) * 32;
    int m0 = blockIdx.y * 128, n0 = blockIdx.x * 128;
    int am = t >> 2, ak = (t & 3) * 4;
    int bk = t >> 5, bn = (t & 31) * 4;

    float c[4][4][4];
#pragma unroll
    for (int i = 0; i < 4; i++)
#pragma unroll
        for (int j = 0; j < 4; j++)
#pragma unroll
            for (int q = 0; q < 4; q++) c[i][j][q] = 0.f;

    auto load = [&](int kt, int buf) {
        const float* Ag = A + (size_t)(m0 + am) * K + kt * 16 + ak;
        cp16(&As[buf][am][ak], Ag);
        cp16(&As[buf][am + 64][ak], Ag + (size_t)64 * K);
        const float* Bg = B + (size_t)(kt * 16 + bk) * N + n0 + bn;
        cp16(&Bs[buf][bk][bn], Bg);
        cp16(&Bs[buf][bk + 8][bn], Bg + (size_t)8 * N);
    };

    int KT = K / 16;
    load(0, 0); CPCOMMIT;
    for (int kt = 0; kt < KT; kt++) {
        int buf = kt & 1;
        if (kt + 1 < KT) { load(kt + 1, buf ^ 1); CPCOMMIT; CPWAIT(1); }
        else { CPWAIT(0); }
        __syncthreads();
#pragma unroll
        for (int ks = 0; ks < 16; ks += 8) {
            unsigned af[4][4], bf[4][2];
#pragma unroll
            for (int i = 0; i < 4; i++) {
                int mr = wm + i * 16 + (lane >> 2);
                int kc = ks + (lane & 3);
                af[i][0] = cvt_tf32(As[buf][mr][kc]);
                af[i][1] = cvt_tf32(As[buf][mr + 8][kc]);
                af[i][2] = cvt_tf32(As[buf][mr][kc + 4]);
                af[i][3] = cvt_tf32(As[buf][mr + 8][kc + 4]);
            }
#pragma unroll
            for (int j = 0; j < 4; j++) {
                int nc = wn + j * 8 + (lane >> 2);
                bf[j][0] = cvt_tf32(Bs[buf][ks + (lane & 3)][nc]);
                bf[j][1] = cvt_tf32(Bs[buf][ks + (lane & 3) + 4][nc]);
            }
#pragma unroll
            for (int i = 0; i < 4; i++)
#pragma unroll
                for (int j = 0; j < 4; j++)
                    mma_tf32(c[i][j], af[i][0], af[i][1], af[i][2], af[i][3],
                             bf[j][0], bf[j][1]);
        }
        __syncthreads();
    }
#pragma unroll
    for (int i = 0; i < 4; i++) {
        int r0 = m0 + wm + i * 16 + (lane >> 2);
#pragma unroll
        for (int j = 0; j < 4; j++) {
            int cc = n0 + wn + j * 8 + (lane & 3) * 2;
            float2 bb = *(const float2*)(bias + cc);
            float2 v0 = {c[i][j][0] + bb.x, c[i][j][1] + bb.y};
            float2 v1 = {c[i][j][2] + bb.x, c[i][j][3] + bb.y};
            *(float2*)(C + (size_t)r0 * N + cc) = v0;
            *(float2*)(C + (size_t)(r0 + 8) * N + cc) = v1;
        }
    }
}

// ---------------------------------------------------------------------------
// Scores: S[bh][q][m] = 0.125 * Q[q,:] . K[m,:]   (K tile kept row-major,
// B-fragments read transposed from it)
// ---------------------------------------------------------------------------
__global__ void __launch_bounds__(256) mm_scores() {
    __shared__ __align__(16) float Qs[2][128][20];
    __shared__ __align__(16) float Ks[2][128][20];
    int bh = blockIdx.z, b = bh / HH, h = bh % HH;
    const float* Q = g_qkv + (size_t)b * NN * 2304 + h * HD;
    const float* Kp = g_qkv + (size_t)b * NN * 2304 + DD + h * HD;
    float* S = g_attn + (size_t)bh * NN * NN;
    int t = threadIdx.x, lane = t & 31, warp = t >> 5;
    int wm = (warp >> 2) * 64, wn = (warp & 3) * 32;
    int m0 = blockIdx.y * 128, n0 = blockIdx.x * 128;
    int am = t >> 2, ak = (t & 3) * 4;

    float c[4][4][4];
#pragma unroll
    for (int i = 0; i < 4; i++)
#pragma unroll
        for (int j = 0; j < 4; j++)
#pragma unroll
            for (int q = 0; q < 4; q++) c[i][j][q] = 0.f;

    auto load = [&](int kt, int buf) {
        const float* Qg = Q + (size_t)(m0 + am) * 2304 + kt * 16 + ak;
        cp16(&Qs[buf][am][ak], Qg);
        cp16(&Qs[buf][am + 64][ak], Qg + (size_t)64 * 2304);
        const float* Kg = Kp + (size_t)(n0 + am) * 2304 + kt * 16 + ak;
        cp16(&Ks[buf][am][ak], Kg);
        cp16(&Ks[buf][am + 64][ak], Kg + (size_t)64 * 2304);
    };

    const int KT = HD / 16;
    load(0, 0); CPCOMMIT;
    for (int kt = 0; kt < KT; kt++) {
        int buf = kt & 1;
        if (kt + 1 < KT) { load(kt + 1, buf ^ 1); CPCOMMIT; CPWAIT(1); }
        else { CPWAIT(0); }
        __syncthreads();
#pragma unroll
        for (int ks = 0; ks < 16; ks += 8) {
            unsigned af[4][4], bf[4][2];
#pragma unroll
            for (int i = 0; i < 4; i++) {
                int mr = wm + i * 16 + (lane >> 2);
                int kc = ks + (lane & 3);
                af[i][0] = cvt_tf32(Qs[buf][mr][kc]);
                af[i][1] = cvt_tf32(Qs[buf][mr + 8][kc]);
                af[i][2] = cvt_tf32(Qs[buf][mr][kc + 4]);
                af[i][3] = cvt_tf32(Qs[buf][mr + 8][kc + 4]);
            }
#pragma unroll
            for (int j = 0; j < 4; j++) {
                int nr = wn + j * 8 + (lane >> 2);
                bf[j][0] = cvt_tf32(Ks[buf][nr][ks + (lane & 3)]);
                bf[j][1] = cvt_tf32(Ks[buf][nr][ks + (lane & 3) + 4]);
            }
#pragma unroll
            for (int i = 0; i < 4; i++)
#pragma unroll
                for (int j = 0; j < 4; j++)
                    mma_tf32(c[i][j], af[i][0], af[i][1], af[i][2], af[i][3],
                             bf[j][0], bf[j][1]);
        }
        __syncthreads();
    }
#pragma unroll
    for (int i = 0; i < 4; i++) {
        int r0 = m0 + wm + i * 16 + (lane >> 2);
#pragma unroll
        for (int j = 0; j < 4; j++) {
            int cc = n0 + wn + j * 8 + (lane & 3) * 2;
            float2 v0 = {c[i][j][0] * 0.125f, c[i][j][1] * 0.125f};
            float2 v1 = {c[i][j][2] * 0.125f, c[i][j][3] * 0.125f};
            *(float2*)(S + (size_t)r0 * NN + cc) = v0;
            *(float2*)(S + (size_t)(r0 + 8) * NN + cc) = v1;
        }
    }
}

// ---------------------------------------------------------------------------
// AV: O[q, h*64+j] = sum_m P[q,m] V[m,j].  128x64x16 tiles.
// ---------------------------------------------------------------------------
__global__ void __launch_bounds__(256) mm_av() {
    __shared__ __align__(16) float As[2][128][20];
    __shared__ __align__(16) float Bs[2][16][72];
    int bh = blockIdx.z, b = bh / HH, h = bh % HH;
    const float* P = g_attn + (size_t)bh * NN * NN;
    const float* V = g_qkv + (size_t)b * NN * 2304 + 2 * DD + h * HD;
    float* O = g_ao + (size_t)b * NN * DD + h * HD;
    int t = threadIdx.x, lane = t & 31, warp = t >> 5;
    int wm = (warp >> 1) * 32, wn = (warp & 1) * 32;
    int m0 = blockIdx.y * 128;
    int am = t >> 2, ak = (t & 3) * 4;
    int bk = t >> 4, bn = (t & 15) * 4;

    float c[2][4][4];
#pragma unroll
    for (int i = 0; i < 2; i++)
#pragma unroll
        for (int j = 0; j < 4; j++)
#pragma unroll
            for (int q = 0; q < 4; q++) c[i][j][q] = 0.f;

    auto load = [&](int kt, int buf) {
        const float* Ag = P + (size_t)(m0 + am) * NN + kt * 16 + ak;
        cp16(&As[buf][am][ak], Ag);
        cp16(&As[buf][am + 64][ak], Ag + (size_t)64 * NN);
        const float* Bg = V + (size_t)(kt * 16 + bk) * 2304 + bn;
        cp16(&Bs[buf][bk][bn], Bg);
    };

    const int KT = NN / 16;
    load(0, 0); CPCOMMIT;
    for (int kt = 0; kt < KT; kt++) {
        int buf = kt & 1;
        if (kt + 1 < KT) { load(kt + 1, buf ^ 1); CPCOMMIT; CPWAIT(1); }
        else { CPWAIT(0); }
        __syncthreads();
#pragma unroll
        for (int ks = 0; ks < 16; ks += 8) {
            unsigned af[2][4], bf[4][2];
#pragma unroll
            for (int i = 0; i < 2; i++) {
                int mr = wm + i * 16 + (lane >> 2);
                int kc = ks + (lane & 3);
                af[i][0] = cvt_tf32(As[buf][mr][kc]);
                af[i][1] = cvt_tf32(As[buf][mr + 8][kc]);
                af[i][2] = cvt_tf32(As[buf][mr][kc + 4]);
                af[i][3] = cvt_tf32(As[buf][mr + 8][kc + 4]);
            }
#pragma unroll
            for (int j = 0; j < 4; j++) {
                int nc = wn + j * 8 + (lane >> 2);
                bf[j][0] = cvt_tf32(Bs[buf][ks + (lane & 3)][nc]);
                bf[j][1] = cvt_tf32(Bs[buf][ks + (lane & 3) + 4][nc]);
            }
#pragma unroll
            for (int i = 0; i < 2; i++)
#pragma unroll
                for (int j = 0; j < 4; j++)
                    mma_tf32(c[i][j], af[i][0], af[i][1], af[i][2], af[i][3],
                             bf[j][0], bf[j][1]);
        }
        __syncthreads();
    }
#pragma unroll
    for (int i = 0; i < 2; i++) {
        int r0 = m0 + wm + i * 16 + (lane >> 2);
#pragma unroll
        for (int j = 0; j < 4; j++) {
            int cc = wn + j * 8 + (lane & 3) * 2;
            float2 v0 = {c[i][j][0], c[i][j][1]};
            float2 v1 = {c[i][j][2], c[i][j][3]};
            *(float2*)(O + (size_t)r0 * DD + cc) = v0;
            *(float2*)(O + (size_t)(r0 + 8) * DD + cc) = v1;
        }
    }
}

// ---------------------------------------------------------------------------
// Threshold selection: pass0 hist (11 bits) -> scan -> candidate gather ->
// final 21-bit select over candidates only.
// ---------------------------------------------------------------------------
__global__ void sel_init() {
    int bh = blockIdx.x, t = threadIdx.x;
    for (int j = t; j < 2048; j += 256) g_hist[bh * 2048 + j] = 0u;
    if (t == 0) g_ccnt[bh] = 0;
}

__global__ void hist0() {
    int bh = blockIdx.y, t = threadIdx.x;
    __shared__ unsigned sh[2048];
    for (int j = t; j < 2048; j += 256) sh[j] = 0u;
    __syncthreads();
    const float4* Sp = (const float4*)(g_attn + (size_t)bh * 1048576) +
                       (size_t)blockIdx.x * 8192;
    for (int i = 0; i < 32; i++) {
        float4 v = Sp[i * 256 + t];
        atomicAdd(&sh[fkey(v.x) >> 21], 1u);
        atomicAdd(&sh[fkey(v.y) >> 21], 1u);
        atomicAdd(&sh[fkey(v.z) >> 21], 1u);
        atomicAdd(&sh[fkey(v.w) >> 21], 1u);
    }
    __syncthreads();
    for (int j = t; j < 2048; j += 256) {
        unsigned cc = sh[j];
        if (cc) atomicAdd(&g_hist[bh * 2048 + j], cc);
    }
}

__global__ void scan0() {
    int bh = blockIdx.x, t = threadIdx.x;
    __shared__ unsigned ssum[256];
    __shared__ int s_sel;
    __shared__ unsigned s_kin;
    const unsigned* hist = g_hist + bh * 2048;
    unsigned loc[8], lsum = 0;
#pragma unroll
    for (int i = 0; i < 8; i++) { loc[i] = hist[t * 8 + i]; lsum += loc[i]; }
    ssum[t] = lsum;
    __syncthreads();
    if (t == 0) {
        unsigned k = KTH, cum = 0, kin = k;
        int sel = 255;
        for (int i = 0; i < 256; i++) {
            if (cum + ssum[i] >= k) { sel = i; kin = k - cum; break; }
            cum += ssum[i];
        }
        s_sel = sel; s_kin = kin;
    }
    __syncthreads();
    if (t == s_sel) {
        unsigned kk = s_kin, cum = 0, d = t * 8 + 7, knew = kk;
#pragma unroll
        for (int i = 0; i < 8; i++) {
            if (cum + loc[i] >= kk) { d = t * 8 + i; knew = kk - cum; break; }
            cum += loc[i];
        }
        g_sel[bh] = d;
        g_krem[bh] = (int)knew;
    }
}

__device__ __forceinline__ void push_cand(unsigned key, unsigned sel,
                                          unsigned* cand, int* cnt,
                                          unsigned lane) {
    bool m = (key >> 21) == sel;
    unsigned bal = __ballot_sync(0xffffffffu, m);
    if (bal) {
        int leader = __ffs(bal) - 1;
        int base = 0;
        if ((int)lane == leader) base = atomicAdd(cnt, __popc(bal));
        base = __shfl_sync(0xffffffffu, base, leader);
        if (m) cand[base + __popc(bal & ((1u << lane) - 1u))] = key;
    }
}

__global__ void cand_pass() {
    int bh = blockIdx.y, t = threadIdx.x;
    unsigned lane = t & 31;
    unsigned sel = g_sel[bh];
    unsigned* cand = g_cand + (size_t)bh * 1048576;
    int* cnt = &g_ccnt[bh];
    const float4* Sp = (const float4*)(g_attn + (size_t)bh * 1048576) +
                       (size_t)blockIdx.x * 8192;
    for (int i = 0; i < 32; i++) {
        float4 v = Sp[i * 256 + t];
        push_cand(fkey(v.x), sel, cand, cnt, lane);
        push_cand(fkey(v.y), sel, cand, cnt, lane);
        push_cand(fkey(v.z), sel, cand, cnt, lane);
        push_cand(fkey(v.w), sel, cand, cnt, lane);
    }
}

__global__ void sel_final() {
    int bh = blockIdx.x, t = threadIdx.x;
    __shared__ unsigned sh[2048];
    __shared__ unsigned ssum[256];
    __shared__ int s_sel;
    __shared__ unsigned s_kin;
    __shared__ unsigned s_b1, s_k2;
    int cnt = g_ccnt[bh];
    const unsigned* cand = g_cand + (size_t)bh * 1048576;

    // pass A: bits 20..10
    for (int j = t; j < 2048; j += 256) sh[j] = 0u;
    __syncthreads();
    for (int i = t; i < cnt; i += 256) atomicAdd(&sh[(cand[i] >> 10) & 2047u], 1u);
    __syncthreads();
    {
        unsigned loc[8], lsum = 0;
#pragma unroll
        for (int i = 0; i < 8; i++) { loc[i] = sh[t * 8 + i]; lsum += loc[i]; }
        ssum[t] = lsum;
        __syncthreads();
        if (t == 0) {
            unsigned k = (unsigned)g_krem[bh], cum = 0, kin = k;
            int sel = 255;
            for (int i = 0; i < 256; i++) {
                if (cum + ssum[i] >= k) { sel = i; kin = k - cum; break; }
                cum += ssum[i];
            }
            s_sel = sel; s_kin = kin;
        }
        __syncthreads();
        if (t == s_sel) {
            unsigned kk = s_kin, cum = 0, d = t * 8 + 7, knew = kk;
#pragma unroll
            for (int i = 0; i < 8; i++) {
                if (cum + loc[i] >= kk) { d = t * 8 + i; knew = kk - cum; break; }
                cum += loc[i];
            }
            s_b1 = d; s_k2 = knew;
        }
        __syncthreads();
    }
    unsigned b1 = s_b1;
    __syncthreads();

    // pass B: bits 9..0
    for (int j = t; j < 1024; j += 256) sh[j] = 0u;
    __syncthreads();
    for (int i = t; i < cnt; i += 256) {
        unsigned ky = cand[i];
        if (((ky >> 10) & 2047u) == b1) atomicAdd(&sh[ky & 1023u], 1u);
    }
    __syncthreads();
    {
        unsigned loc[4], lsum = 0;
#pragma unroll
        for (int i = 0; i < 4; i++) { loc[i] = sh[t * 4 + i]; lsum += loc[i]; }
        ssum[t] = lsum;
        __syncthreads();
        if (t == 0) {
            unsigned k = s_k2, cum = 0, kin = k;
            int sel = 255;
            for (int i = 0; i < 256; i++) {
                if (cum + ssum[i] >= k) { sel = i; kin = k - cum; break; }
                cum += ssum[i];
            }
            s_sel = sel; s_kin = kin;
        }
        __syncthreads();
        if (t == s_sel) {
            unsigned kk = s_kin, cum = 0, d = t * 4 + 3;
#pragma unroll
            for (int i = 0; i < 4; i++) {
                if (cum + loc[i] >= kk) { d = t * 4 + i; break; }
                cum += loc[i];
            }
            unsigned key = (g_sel[bh] << 21) | (b1 << 10) | d;
            unsigned bits = (key & 0x80000000u) ? (key ^ 0x80000000u) : ~key;
            g_thr[bh] = __uint_as_float(bits);
        }
    }
}

// ---------------------------------------------------------------------------
// Masked softmax (float4, one block per row, in place)
// ---------------------------------------------------------------------------
__global__ void softmax_mask() {
    int row = blockIdx.x, bh = row >> 10;
    float thr = g_thr[bh];
    float4* S = (float4*)(g_attn + (size_t)row * NN);
    int t = threadIdx.x;
    unsigned lane = t & 31, w = t >> 5;
    __shared__ float red[8];

    float4 vv = S[t];
    float v[4] = {vv.x, vv.y, vv.z, vv.w};
    float mx = -3.0e38f;
#pragma unroll
    for (int i = 0; i < 4; i++) {
        v[i] = (v[i] <= thr) ? -1e9f : v[i];
        mx = fmaxf(mx, v[i]);
    }
#pragma unroll
    for (int o = 16; o; o >>= 1) mx = fmaxf(mx, __shfl_xor_sync(0xffffffffu, mx, o));
    if (lane == 0) red[w] = mx;
    __syncthreads();
    float m = red[0];
#pragma unroll
    for (int i = 1; i < 8; i++) m = fmaxf(m, red[i]);

    float e[4], s = 0.f;
#pragma unroll
    for (int i = 0; i < 4; i++) { e[i] = __expf(v[i] - m); s += e[i]; }
#pragma unroll
    for (int o = 16; o; o >>= 1) s += __shfl_xor_sync(0xffffffffu, s, o);
    __syncthreads();
    if (lane == 0) red[w] = s;
    __syncthreads();
    float tot = 0.f;
#pragma unroll
    for (int i = 0; i < 8; i++) tot += red[i];
    float inv = 1.f / tot;
    float4 ov = {e[0] * inv, e[1] * inv, e[2] * inv, e[3] * inv};
    S[t] = ov;
}

// ---------------------------------------------------------------------------
extern "C" void kernel_launch(void* const* d_in, const int* in_sizes, int n_in,
                              void* d_out, int out_size) {
    const float* x = (const float*)d_in[0];
    const float* W_qkv = (const float*)d_in[1];
    const float* b_qkv = (const float*)d_in[2];
    const float* W_out = (const float*)d_in[3];
    const float* b_out = (const float*)d_in[4];
    float* out = (float*)d_out;

    float* qkv_p; cudaGetSymbolAddress((void**)&qkv_p, g_qkv);
    float* ao_p;  cudaGetSymbolAddress((void**)&ao_p, g_ao);

    // 1. QKV projection
    mm_proj<<<dim3(2304 / 128, 4096 / 128), 256>>>(x, W_qkv, b_qkv, qkv_p, 2304, 768);
    // 2. Scores
    mm_scores<<<dim3(8, 8, BH), 256>>>();
    // 3. Threshold (exact kth smallest)
    sel_init<<<BH, 256>>>();
    hist0<<<dim3(32, BH), 256>>>();
    scan0<<<BH, 256>>>();
    cand_pass<<<dim3(32, BH), 256>>>();
    sel_final<<<BH, 256>>>();
    // 4. Masked softmax
    softmax_mask<<<BH * NN, 256>>>();
    // 5. P @ V
    mm_av<<<dim3(1, 8, BH), 256>>>();
    // 6. Output projection
    mm_proj<<<dim3(768 / 128, 4096 / 128), 256>>>(ao_p, W_out, b_out, out, 768, 768);
}